// round 8
// baseline (speedup 1.0000x reference)
#include <cuda_runtime.h>

#define BINS 64
#define BC 96                      // B*C = 32*3
#define PLANE 262144               // 512*512 per (b,c) plane
#define BPP 32                     // blocks per plane
#define CHUNK (PLANE / BPP)        // 8192 floats per block per tensor
#define THREADS 128
#define WARPS (THREADS / 32)       // 4
#define N4 (CHUNK / 4)             // 2048 float4 per block per tensor
#define GRID (BC * BPP)            // 3072 blocks

// Signed per-(plane,bin) count diff (+input, -target). Zero at module load;
// the last block restores it to zero each call -> graph-replay safe.
__device__ int g_diff[BC * BINS];
__device__ unsigned int g_count;

// bin = clip(floor((v+1)/step), 0, 63). Input domain [-1,1) => result >= 0.
// Exact-edge disagreement with searchsorted is ~1e-6 relative loss noise.
__device__ __forceinline__ int bin_of(float v) {
    return min(__float2int_rd(fmaf(v, 31.5f, 31.5f)), 63);
}

__global__ __launch_bounds__(THREADS)
void fused_kernel(const float4* __restrict__ inp, const float4* __restrict__ tgt,
                  float* __restrict__ out) {
    // Per-WARP private s8 histograms: byte slot = w*2048 + bin*32 + lane.
    // Quad lanes share a word (byte-merged); quads hit banks (8*bin+quad)%32
    // -> ~2-way worst conflicts. 8 KB/block => thread-limited 16 blocks/SM
    // = 64 warps = full residency. Range: <=64 values/tensor/thread -> s8 ok.
    __shared__ signed char hist[WARPS * BINS * 32];   // 8 KB
    __shared__ unsigned int s_ticket;
    __shared__ float ssum[WARPS];

    const int tid  = threadIdx.x;
    const int lane = tid & 31;
    const int wid  = tid >> 5;

    int4* h4 = (int4*)hist;
    #pragma unroll
    for (int i = tid; i < (int)sizeof(hist) / 16; i += THREADS)
        h4[i] = make_int4(0, 0, 0, 0);
    __syncthreads();

    signed char* h = &hist[wid * BINS * 32 + lane];   // lane-owned byte column

    const int plane = blockIdx.x / BPP;
    const int chunk = blockIdx.x % BPP;
    const size_t base4 = (size_t)plane * (PLANE / 4) + (size_t)chunk * N4;
    const float4* __restrict__ a = inp + base4;
    const float4* __restrict__ b = tgt + base4;

    #pragma unroll 4
    for (int i = tid; i < N4; i += THREADS) {
        float4 v = __ldcs(&a[i]);               // read-once: streaming
        float4 u = __ldcs(&b[i]);
        h[bin_of(v.x) * 32] += 1;
        h[bin_of(v.y) * 32] += 1;
        h[bin_of(v.z) * 32] += 1;
        h[bin_of(v.w) * 32] += 1;
        h[bin_of(u.x) * 32] -= 1;
        h[bin_of(u.y) * 32] -= 1;
        h[bin_of(u.z) * 32] -= 1;
        h[bin_of(u.w) * 32] -= 1;
    }
    __syncthreads();

    // Fold: thread t -> bin = t&63, grp = t>>6 summing warps {2g, 2g+1}.
    // Per (warp,bin): 32 s8 = 8 words, signed-summed via dp4a.
    {
        const int bin = tid & 63;
        const int grp = tid >> 6;
        int s = 0;
        #pragma unroll
        for (int w = 0; w < 2; w++) {
            const int* row = (const int*)&hist[(2 * grp + w) * BINS * 32 + bin * 32];
            #pragma unroll
            for (int k = 0; k < 8; k++)
                s = __dp4a(row[(k + bin) & 7], 0x01010101, s);  // signed bytes
        }
        if (s != 0) atomicAdd(&g_diff[plane * BINS + bin], s);
    }

    // Last block finishes the reduction (no separate kernel launch).
    __threadfence();
    if (tid == 0) s_ticket = atomicAdd(&g_count, 1u);
    __syncthreads();
    if (s_ticket == GRID - 1) {
        float s = 0.0f;
        for (int i = tid; i < BC * BINS; i += THREADS) {
            s += fabsf((float)__ldcg(&g_diff[i]));
            g_diff[i] = 0;                      // restore scratch for replay
        }
        #pragma unroll
        for (int o = 16; o > 0; o >>= 1)
            s += __shfl_down_sync(0xFFFFFFFFu, s, o);
        if (lane == 0) ssum[wid] = s;
        __syncthreads();
        if (tid == 0) {
            float t = ssum[0] + ssum[1] + ssum[2] + ssum[3];
            out[0] = t / ((float)PLANE * (float)(BC * BINS));
            g_count = 0u;                       // restore ticket for replay
        }
    }
}

extern "C" void kernel_launch(void* const* d_in, const int* in_sizes, int n_in,
                              void* d_out, int out_size) {
    const float* inp = (const float*)d_in[0];
    const float* tgt = (const float*)d_in[1];
    float* out = (float*)d_out;

    fused_kernel<<<GRID, THREADS>>>((const float4*)inp, (const float4*)tgt, out);
}

// round 9
// speedup vs baseline: 1.1642x; 1.1642x over previous
#include <cuda_runtime.h>

#define BINS 64
#define BC 96                      // B*C = 32*3
#define PLANE 262144               // 512*512 per (b,c) plane
#define BPP 32                     // blocks per plane
#define CHUNK (PLANE / BPP)        // 8192 floats per block per tensor
#define THREADS 128
#define WARPS (THREADS / 32)       // 4
#define N4 (CHUNK / 4)             // 2048 float4 per block per tensor
#define GRID (BC * BPP)            // 3072 blocks

// Signed per-(plane,bin) count diff (+input, -target). Zero at module load;
// the last block restores it to zero each call -> graph-replay safe.
__device__ int g_diff[BC * BINS];
__device__ unsigned int g_count;

// bin = clip(floor((v+1)/step), 0, 63). Input domain [-1,1) => result >= 0.
// Exact-edge disagreement with searchsorted is ~1e-6 relative loss noise.
__device__ __forceinline__ int bin_of(float v) {
    return min(__float2int_rd(fmaf(v, 31.5f, 31.5f)), 63);
}

// Halfword offset within a lane's column: two bins share one 32-bit word.
// word(w, m, lane) = w*1024 + m*32 + lane  (m = bin>>1), halfword = bin&1.
// word % 32 == lane for EVERY bin -> strictly conflict-free LDS/STS RMW.
__device__ __forceinline__ int slot_of(int b) {
    return ((b >> 1) << 6) | (b & 1);          // halfword units, per-lane base
}

__global__ __launch_bounds__(THREADS)
void fused_kernel(const float4* __restrict__ inp, const float4* __restrict__ tgt,
                  float* __restrict__ out) {
    __shared__ short hist[WARPS * BINS * 32];  // 16 KB -> 14 blocks/SM
    __shared__ unsigned int s_ticket;
    __shared__ float ssum[WARPS];

    const int tid  = threadIdx.x;
    const int lane = tid & 31;
    const int wid  = tid >> 5;

    int4* z4 = (int4*)hist;
    #pragma unroll
    for (int i = tid; i < (int)sizeof(hist) / 16; i += THREADS)
        z4[i] = make_int4(0, 0, 0, 0);
    __syncthreads();

    // Lane-owned column: halfword index = wid*2048 + lane*2 + slot_of(bin).
    short* h = &hist[wid * 2048 + lane * 2];

    const int plane = blockIdx.x / BPP;
    const int chunk = blockIdx.x % BPP;
    const size_t base4 = (size_t)plane * (PLANE / 4) + (size_t)chunk * N4;
    const float4* __restrict__ a = inp + base4;
    const float4* __restrict__ b = tgt + base4;

    #pragma unroll 4
    for (int i = tid; i < N4; i += THREADS) {
        float4 v = __ldcs(&a[i]);              // read-once: streaming
        float4 u = __ldcs(&b[i]);
        h[slot_of(bin_of(v.x))] += 1;
        h[slot_of(bin_of(v.y))] += 1;
        h[slot_of(bin_of(v.z))] += 1;
        h[slot_of(bin_of(v.w))] += 1;
        h[slot_of(bin_of(u.x))] -= 1;
        h[slot_of(bin_of(u.y))] -= 1;
        h[slot_of(bin_of(u.z))] -= 1;
        h[slot_of(bin_of(u.w))] -= 1;
    }
    __syncthreads();

    // Fold: thread t -> bin pair m = t>>2, warp w = t&3. Packed halfword
    // accumulation over 32 lanes (__vadd2: no cross-half carry; |sums| <=
    // 8192 << 32767). Rotation (k+t)&31 keeps banks distinct across the
    // fold warp. Then shfl-combine the 4 warps (groups of 4 lanes).
    {
        const int m = tid >> 2;
        const int w = tid & 3;
        const int* words = (const int*)hist;
        int sp = 0;
        #pragma unroll
        for (int k = 0; k < 32; k++)
            sp = __vadd2(sp, words[w * 1024 + m * 32 + ((k + tid) & 31)]);
        sp = __vadd2(sp, __shfl_xor_sync(0xFFFFFFFFu, sp, 1));
        sp = __vadd2(sp, __shfl_xor_sync(0xFFFFFFFFu, sp, 2));
        if (w == 0) {
            int s_even = (int)(short)(sp & 0xFFFF);
            int s_odd  = sp >> 16;
            if (s_even) atomicAdd(&g_diff[plane * BINS + 2 * m], s_even);
            if (s_odd)  atomicAdd(&g_diff[plane * BINS + 2 * m + 1], s_odd);
        }
    }

    // Last block finishes the reduction (no separate kernel launch).
    __threadfence();
    if (tid == 0) s_ticket = atomicAdd(&g_count, 1u);
    __syncthreads();
    if (s_ticket == GRID - 1) {
        float s = 0.0f;
        for (int i = tid; i < BC * BINS; i += THREADS) {
            s += fabsf((float)__ldcg(&g_diff[i]));
            g_diff[i] = 0;                     // restore scratch for replay
        }
        #pragma unroll
        for (int o = 16; o > 0; o >>= 1)
            s += __shfl_down_sync(0xFFFFFFFFu, s, o);
        if (lane == 0) ssum[wid] = s;
        __syncthreads();
        if (tid == 0) {
            float t = ssum[0] + ssum[1] + ssum[2] + ssum[3];
            out[0] = t / ((float)PLANE * (float)(BC * BINS));
            g_count = 0u;                      // restore ticket for replay
        }
    }
}

extern "C" void kernel_launch(void* const* d_in, const int* in_sizes, int n_in,
                              void* d_out, int out_size) {
    const float* inp = (const float*)d_in[0];
    const float* tgt = (const float*)d_in[1];
    float* out = (float*)d_out;

    fused_kernel<<<GRID, THREADS>>>((const float4*)inp, (const float4*)tgt, out);
}